// round 16
// baseline (speedup 1.0000x reference)
#include <cuda_runtime.h>
#include <cuda_bf16.h>
#include <cuda_fp16.h>
#include <cstdint>

#define N_NODES 100000
#define N_HE    30000
#define N_INC   300000
#define IN_CH   128
#define HID     256
#define OUT_CH  128
#define BN_EPS  1e-5f

// ---------------- device scratch (allocation-free) ----------------
__device__ __half g_X1[(size_t)N_NODES * HID];          // node features fp16
__device__ __half g_HEW[(size_t)N_HE * HID];            // hyperedge features after GEMM fp16
__device__ __half g_W1s[(size_t)HID * 2 * IN_CH];       // [256, 256] = [hi|lo]
__device__ __half g_W2s[(size_t)HID * 2 * HID];         // [256, 512]
__device__ __half g_W3s[(size_t)OUT_CH * 2 * HID];      // [128, 512]

__device__ int g_nd_cnt[N_NODES];
__device__ int g_he_cnt[N_HE];
__device__ int g_nd_off[N_NODES + 1];
__device__ int g_he_off[N_HE + 1];
__device__ int g_nd_hes[N_INC];
__device__ int g_he_nodes[N_INC];
__device__ int g_bsum[64];
__device__ int g_scan_ctr;

__device__ float g_bnst[2 * 2 * HID];   // set0: [0..511], set1: [512..1023]; each [sum(256)|sumsq(256)]

// ---------------- helpers ----------------
__device__ __forceinline__ uint32_t smem_to_u32(const void* p) {
    uint32_t a;
    asm("{ .reg .u64 t; cvta.to.shared.u64 t, %1; cvt.u32.u64 %0, t; }" : "=r"(a) : "l"(p));
    return a;
}
#define SWZ(off) ((off) ^ (((off) >> 3) & 0x70))

__device__ __forceinline__ void cp_async16(uint32_t dst, const void* src) {
    asm volatile("cp.async.cg.shared.global [%0], [%1], 16;" :: "r"(dst), "l"(src) : "memory");
}
__device__ __forceinline__ uint32_t pack_h2(float x, float y) {
    __half2 h = __floats2half2_rn(x, y);
    return *reinterpret_cast<uint32_t*>(&h);
}
__device__ __forceinline__ float2 unpack_h2(uint32_t u) {
    __half2 h = *reinterpret_cast<__half2*>(&u);
    return __half22float2(h);
}
__device__ __forceinline__ void acc_h2(float4& acc, uint2 u2) {
    float2 v0 = unpack_h2(u2.x);
    float2 v1 = unpack_h2(u2.y);
    acc.x += v0.x; acc.y += v0.y; acc.z += v1.x; acc.w += v1.y;
}

// ---------------- CSR build ----------------
__global__ void k_hist(const int* __restrict__ node_idx, const int* __restrict__ he_idx) {
    int i = blockIdx.x * blockDim.x + threadIdx.x;
    if (i < N_INC) {
        atomicAdd(&g_nd_cnt[node_idx[i]], 1);
        atomicAdd(&g_he_cnt[he_idx[i]], 1);
    }
}

// single-kernel exclusive scan over BOTH cnt arrays (all blocks resident).
// Publishes per-block sums, spins on a counter, then each block applies its base.
// Also re-zeroes cnt for the subsequent scatter pass and writes off[n] totals.
__global__ void __launch_bounds__(256) k_scan_all(int nb_nd) {
    bool he = (int)blockIdx.x >= nb_nd;
    int* cnt = he ? g_he_cnt : g_nd_cnt;
    int n = he ? N_HE : N_NODES;
    int bid = he ? (int)blockIdx.x - nb_nd : (int)blockIdx.x;
    int* off = he ? g_he_off : g_nd_off;
    int tid = threadIdx.x;
    int base = bid * 2048;
    int v[8];
    int s = 0;
#pragma unroll
    for (int i = 0; i < 8; i++) {
        int idx = base + tid * 8 + i;
        v[i] = (idx < n) ? cnt[idx] : 0;
        s += v[i];
    }
    int lane = tid & 31, w = tid >> 5;
    int x = s;
#pragma unroll
    for (int o = 1; o < 32; o <<= 1) {
        int t = __shfl_up_sync(0xFFFFFFFFu, x, o);
        if (lane >= o) x += t;
    }
    __shared__ int ws[8];
    __shared__ int wexcl[8];
    __shared__ int sbase;
    if (lane == 31) ws[w] = x;
    __syncthreads();
    if (tid < 8) {
        int t = 0;
        for (int j = 0; j < tid; j++) t += ws[j];
        wexcl[tid] = t;
    }
    if (tid == 0) {
        int tot = 0;
#pragma unroll
        for (int j = 0; j < 8; j++) tot += ws[j];
        g_bsum[blockIdx.x] = tot;
        __threadfence();
        atomicAdd(&g_scan_ctr, 1);
        while (atomicAdd(&g_scan_ctr, 0) < (int)gridDim.x) {}
        int lo = he ? nb_nd : 0;
        int b = 0;
        for (int j = lo; j < (int)blockIdx.x; j++)
            b += *((volatile int*)&g_bsum[j]);
        sbase = b;
    }
    __syncthreads();
    int run = sbase + wexcl[w] + (x - s);
#pragma unroll
    for (int i = 0; i < 8; i++) {
        int idx = base + tid * 8 + i;
        if (idx < n) {
            off[idx] = run;
            cnt[idx] = 0;          // re-zero for scatter
            run += v[i];
            if (idx == n - 1) off[n] = run;
        }
    }
}

__global__ void k_scatter(const int* __restrict__ node_idx, const int* __restrict__ he_idx) {
    int i = blockIdx.x * blockDim.x + threadIdx.x;
    if (i < N_INC) {
        int n = node_idx[i], e = he_idx[i];
        int p = atomicAdd(&g_he_cnt[e], 1);
        g_he_nodes[g_he_off[e] + p] = n;
        int q = atomicAdd(&g_nd_cnt[n], 1);
        g_nd_hes[g_nd_off[n] + q] = e;
    }
}

// ---------------- fused weight split + ALL zeroing (one launch) ----------------
__device__ __forceinline__ void split_one(const float* __restrict__ W, __half* __restrict__ Ws,
                                          int K, int N, int i) {
    int k = i / N, n = i - k * N;
    float v = W[i];
    __half h = __float2half_rn(v);
    __half l = __float2half_rn(v - __half2float(h));
    __half* O = Ws + (size_t)n * 2 * K;
    O[k] = h;
    O[K + k] = l;
}
__global__ void k_split_W_all(const float* __restrict__ W1, const float* __restrict__ W2,
                              const float* __restrict__ W3) {
    int i = blockIdx.x * blockDim.x + threadIdx.x;
    if (i < 32768)        split_one(W1, g_W1s, IN_CH, HID, i);
    else if (i < 98304)   split_one(W2, g_W2s, HID, HID, i - 32768);
    else if (i < 131072)  split_one(W3, g_W3s, HID, OUT_CH, i - 98304);
    if (i < N_NODES) g_nd_cnt[i] = 0;
    else if (i < N_NODES + N_HE) g_he_cnt[i - N_NODES] = 0;
    if (i < 2 * 2 * HID) g_bnst[i] = 0.f;
    if (i == 0) g_scan_ctr = 0;
}

// ---------------- GEMM with fused hyperedge gather in the A-prologue ----------------
// C[M,N]fp16 = gatherA[M,K] @ (Bh+Bl)[N,2K]fp16^T
// A-tile (128 hyperedge rows) gathered from node features via he-CSR into smem,
// averaged, optionally BN-affine'd (MODE 1), fp16-converted, swizzled. A stays
// resident; B streams in K-chunks (hi+lo halves), double-buffered cp.async.
// MODE 0: Xsrc = fp32 x [*, K]   (layer 1, no BN)
// MODE 1: Xsrc = fp16 X1 [*, K] with BN from bnst_in/gam/bet (layers 2/3)
template <int NWN, int K, int MODE>
__global__ void __launch_bounds__(NWN * 128, 1)
gemm_gather(const void* __restrict__ Xsrc, const __half* __restrict__ Bw,
            __half* __restrict__ C, int M,
            const float* __restrict__ gam, const float* __restrict__ bet,
            const float* __restrict__ bnst_in)
{
    constexpr int N = NWN * 64;
    constexpr int NT = NWN * 128;
    constexpr int K64 = K / 64;
    constexpr uint32_t ABYTES = (uint32_t)K64 * 16384;
    constexpr uint32_t NB = (uint32_t)N * 128;
    extern __shared__ char smc[];
    const uint32_t tbase = smem_to_u32(smc);
    const int tid  = threadIdx.x;
    const int lane = tid & 31;
    const int wid  = tid >> 5;
    const int wm   = wid / NWN;
    const int wn   = wid % NWN;
    const int row0 = blockIdx.y * 128;
    const int Kt   = 2 * K;

    auto loadB = [&](int c, int buf) {
        uint32_t bb = tbase + ABYTES + (uint32_t)buf * (2 * NB);
#pragma unroll
        for (int t = 0; t < 2; t++) {
            const __half* Bg = Bw + (size_t)(c + t * K64) * 64;
            for (int i = tid; i < N * 8; i += NT) {
                int r = i >> 3, q = i & 7;
                cp_async16(bb + t * NB + SWZ((uint32_t)(r * 128 + q * 16)),
                           Bg + (size_t)r * Kt + q * 8);
            }
        }
        asm volatile("cp.async.commit_group;" ::: "memory");
    };

    // kick off first B chunk while we gather A
    loadB(0, 0);

    // ---- gather A tile (128 rows x K fp16) into chunked swizzled smem ----
    {
        constexpr int F4 = K / 4;         // uint2 lanes per row
        constexpr int NSUB = NT / F4;     // rows in flight
        int f4 = tid & (F4 - 1);
        int sub = tid / F4;
        float sc[4], sh[4];
        if (MODE == 1) {
            int c = f4 * 4;
            const float invN = 1.0f / (float)N_NODES;
#pragma unroll
            for (int u = 0; u < 4; u++) {
                float m = bnst_in[c + u] * invN;
                float var = bnst_in[HID + c + u] * invN - m * m;
                float s = gam[c + u] * rsqrtf(var + BN_EPS);
                sc[u] = s;
                sh[u] = bet[c + u] - m * s;
            }
        }
#pragma unroll
        for (int i = 0; i < 128 / NSUB; i++) {
            int r = i * NSUB + sub;
            int e = row0 + r;
            uint2 outv = make_uint2(0u, 0u);
            if (e < M) {
                int s = g_he_off[e], t = g_he_off[e + 1];
                float4 acc = make_float4(0.f, 0.f, 0.f, 0.f);
                int j = s;
                if (MODE == 0) {
                    const float4* X = reinterpret_cast<const float4*>(Xsrc);
                    for (; j + 2 <= t; j += 2) {
                        int n0 = g_he_nodes[j], n1 = g_he_nodes[j + 1];
                        float4 v0 = X[(size_t)n0 * F4 + f4];
                        float4 v1 = X[(size_t)n1 * F4 + f4];
                        acc.x += v0.x + v1.x; acc.y += v0.y + v1.y;
                        acc.z += v0.z + v1.z; acc.w += v0.w + v1.w;
                    }
                    for (; j < t; j++) {
                        float4 v = X[(size_t)g_he_nodes[j] * F4 + f4];
                        acc.x += v.x; acc.y += v.y; acc.z += v.z; acc.w += v.w;
                    }
                } else {
                    const uint2* X = reinterpret_cast<const uint2*>(Xsrc);
                    for (; j + 4 <= t; j += 4) {
                        int n0 = g_he_nodes[j], n1 = g_he_nodes[j + 1];
                        int n2 = g_he_nodes[j + 2], n3 = g_he_nodes[j + 3];
                        uint2 u0 = X[(size_t)n0 * F4 + f4];
                        uint2 u1 = X[(size_t)n1 * F4 + f4];
                        uint2 u2 = X[(size_t)n2 * F4 + f4];
                        uint2 u3 = X[(size_t)n3 * F4 + f4];
                        acc_h2(acc, u0); acc_h2(acc, u1); acc_h2(acc, u2); acc_h2(acc, u3);
                    }
                    for (; j < t; j++)
                        acc_h2(acc, X[(size_t)g_he_nodes[j] * F4 + f4]);
                }
                if (t > s) {
                    float inv = 1.0f / (float)(t - s);
                    float4 o;
                    if (MODE == 1) {
                        o.x = (acc.x * inv) * sc[0] + sh[0];
                        o.y = (acc.y * inv) * sc[1] + sh[1];
                        o.z = (acc.z * inv) * sc[2] + sh[2];
                        o.w = (acc.w * inv) * sc[3] + sh[3];
                    } else {
                        o.x = acc.x * inv; o.y = acc.y * inv;
                        o.z = acc.z * inv; o.w = acc.w * inv;
                    }
                    outv = make_uint2(pack_h2(o.x, o.y), pack_h2(o.z, o.w));
                }
            }
            uint32_t chunk = (uint32_t)(f4 >> 4);
            uint32_t off = chunk * 16384 + SWZ((uint32_t)(r * 128 + (f4 & 15) * 8));
            *reinterpret_cast<uint2*>(smc + off) = outv;
        }
    }

    float acc[2][8][4];
#pragma unroll
    for (int i = 0; i < 2; i++)
#pragma unroll
        for (int j = 0; j < 8; j++)
#pragma unroll
            for (int k = 0; k < 4; k++) acc[i][j][k] = 0.f;

    uint32_t a_off[2], b_off[4];
#pragma unroll
    for (int mf = 0; mf < 2; mf++)
        a_off[mf] = (uint32_t)((wm * 32 + mf * 16 + (lane & 15)) * 128 + (lane >> 4) * 16);
#pragma unroll
    for (int nf4 = 0; nf4 < 4; nf4++)
        b_off[nf4] = (uint32_t)((wn * 64 + nf4 * 16 + (lane & 7) + ((lane >> 4) & 1) * 8) * 128
                                + ((lane >> 3) & 1) * 16);

    for (int c = 0; c < K64; c++) {
        int buf = c & 1;
        if (c + 1 < K64) {
            loadB(c + 1, buf ^ 1);
            asm volatile("cp.async.wait_group 1;" ::: "memory");
        } else {
            asm volatile("cp.async.wait_group 0;" ::: "memory");
        }
        __syncthreads();   // first iteration: also covers the A-gather stores

        uint32_t ab = tbase + (uint32_t)c * 16384;
        uint32_t bb = tbase + ABYTES + (uint32_t)buf * (2 * NB);
#pragma unroll
        for (int k16 = 0; k16 < 4; k16++) {
            uint32_t a[2][4];
#pragma unroll
            for (int mf = 0; mf < 2; mf++) {
                uint32_t addr = ab + SWZ(a_off[mf] + (uint32_t)(k16 * 32));
                asm volatile("ldmatrix.sync.aligned.m8n8.x4.shared.b16 {%0,%1,%2,%3}, [%4];"
                             : "=r"(a[mf][0]), "=r"(a[mf][1]), "=r"(a[mf][2]), "=r"(a[mf][3])
                             : "r"(addr));
            }
#pragma unroll
            for (int t = 0; t < 2; t++) {
                uint32_t b[4][4];
#pragma unroll
                for (int nf4 = 0; nf4 < 4; nf4++) {
                    uint32_t addr = bb + t * NB + SWZ(b_off[nf4] + (uint32_t)(k16 * 32));
                    asm volatile("ldmatrix.sync.aligned.m8n8.x4.shared.b16 {%0,%1,%2,%3}, [%4];"
                                 : "=r"(b[nf4][0]), "=r"(b[nf4][1]), "=r"(b[nf4][2]), "=r"(b[nf4][3])
                                 : "r"(addr));
                }
#pragma unroll
                for (int mf = 0; mf < 2; mf++)
#pragma unroll
                    for (int nf = 0; nf < 8; nf++) {
                        asm volatile(
                            "mma.sync.aligned.m16n8k16.row.col.f32.f16.f16.f32 "
                            "{%0,%1,%2,%3}, {%4,%5,%6,%7}, {%8,%9}, {%0,%1,%2,%3};"
                            : "+f"(acc[mf][nf][0]), "+f"(acc[mf][nf][1]),
                              "+f"(acc[mf][nf][2]), "+f"(acc[mf][nf][3])
                            : "r"(a[mf][0]), "r"(a[mf][1]), "r"(a[mf][2]), "r"(a[mf][3]),
                              "r"(b[nf >> 1][(nf & 1) * 2]), "r"(b[nf >> 1][(nf & 1) * 2 + 1]));
                    }
            }
        }
        __syncthreads();
    }

#pragma unroll
    for (int mf = 0; mf < 2; mf++) {
        int r0g = row0 + wm * 32 + mf * 16 + (lane >> 2);
        int r1g = r0g + 8;
#pragma unroll
        for (int nf = 0; nf < 8; nf++) {
            int col = wn * 64 + nf * 8 + (lane & 3) * 2;
            uint32_t v0 = pack_h2(acc[mf][nf][0], acc[mf][nf][1]);
            uint32_t v1 = pack_h2(acc[mf][nf][2], acc[mf][nf][3]);
            if (r0g < M) *reinterpret_cast<uint32_t*>(C + (size_t)r0g * N + col) = v0;
            if (r1g < M) *reinterpret_cast<uint32_t*>(C + (size_t)r1g * N + col) = v1;
        }
    }
}

// ---------------- node gather kernels ----------------
// F=256 + bias + relu + fused BN-stats: HEW fp16 -> X1 fp16
__global__ void __launch_bounds__(256) k_node_gather_bn(const __half* __restrict__ HEW,
                                                        const float* __restrict__ bias,
                                                        __half* __restrict__ OUT,
                                                        float* __restrict__ bnst_out) {
    __shared__ float rs[4][HID];
    __shared__ float rq[4][HID];
    int tid = threadIdx.x;
    int f4 = tid & 63;
    int sub = tid >> 6;              // 0..3
    int c = f4 * 4;
    float4 b4 = reinterpret_cast<const float4*>(bias)[f4];
    float s4[4] = {0.f, 0.f, 0.f, 0.f};
    float q4[4] = {0.f, 0.f, 0.f, 0.f};
    int base = blockIdx.x * 128;
#pragma unroll 4
    for (int i = 0; i < 32; i++) {
        int n = base + i * 4 + sub;
        if (n >= N_NODES) break;
        int s = g_nd_off[n], t = g_nd_off[n + 1];
        float4 acc = make_float4(0.f, 0.f, 0.f, 0.f);
        int j = s;
        for (; j + 4 <= t; j += 4) {
            int e0 = g_nd_hes[j], e1 = g_nd_hes[j + 1];
            int e2 = g_nd_hes[j + 2], e3 = g_nd_hes[j + 3];
            uint2 u0 = reinterpret_cast<const uint2*>(HEW)[(size_t)e0 * 64 + f4];
            uint2 u1 = reinterpret_cast<const uint2*>(HEW)[(size_t)e1 * 64 + f4];
            uint2 u2 = reinterpret_cast<const uint2*>(HEW)[(size_t)e2 * 64 + f4];
            uint2 u3 = reinterpret_cast<const uint2*>(HEW)[(size_t)e3 * 64 + f4];
            acc_h2(acc, u0); acc_h2(acc, u1); acc_h2(acc, u2); acc_h2(acc, u3);
        }
        for (; j < t; j++)
            acc_h2(acc, reinterpret_cast<const uint2*>(HEW)[(size_t)g_nd_hes[j] * 64 + f4]);
        float inv = (t > s) ? 1.0f / (float)(t - s) : 0.f;
        float4 o;
        o.x = fmaxf(fmaf(acc.x, inv, b4.x), 0.f);
        o.y = fmaxf(fmaf(acc.y, inv, b4.y), 0.f);
        o.z = fmaxf(fmaf(acc.z, inv, b4.z), 0.f);
        o.w = fmaxf(fmaf(acc.w, inv, b4.w), 0.f);
        reinterpret_cast<uint2*>(OUT)[(size_t)n * 64 + f4] =
            make_uint2(pack_h2(o.x, o.y), pack_h2(o.z, o.w));
        s4[0] += o.x; s4[1] += o.y; s4[2] += o.z; s4[3] += o.w;
        q4[0] += o.x * o.x; q4[1] += o.y * o.y; q4[2] += o.z * o.z; q4[3] += o.w * o.w;
    }
#pragma unroll
    for (int u = 0; u < 4; u++) {
        rs[sub][c + u] = s4[u];
        rq[sub][c + u] = q4[u];
    }
    __syncthreads();
    if (sub == 0) {
#pragma unroll
        for (int u = 0; u < 4; u++) {
            float ts = rs[0][c + u] + rs[1][c + u] + rs[2][c + u] + rs[3][c + u];
            float tq = rq[0][c + u] + rq[1][c + u] + rq[2][c + u] + rq[3][c + u];
            atomicAdd(&bnst_out[c + u], ts);
            atomicAdd(&bnst_out[HID + c + u], tq);
        }
    }
}

// F=128 + bias + relu -> out fp32 (layer 3)
__global__ void __launch_bounds__(256) k_node_gather128(const __half* __restrict__ HEW,
                                                        const float* __restrict__ bias,
                                                        float* __restrict__ OUT) {
    int tid = threadIdx.x;
    int f4 = tid & 31;
    int sub = tid >> 5;              // 0..7
    float4 b4 = reinterpret_cast<const float4*>(bias)[f4];
    int base = blockIdx.x * 128;
#pragma unroll 4
    for (int i = 0; i < 16; i++) {
        int n = base + i * 8 + sub;
        if (n >= N_NODES) break;
        int s = g_nd_off[n], t = g_nd_off[n + 1];
        float4 acc = make_float4(0.f, 0.f, 0.f, 0.f);
        int j = s;
        for (; j + 4 <= t; j += 4) {
            int e0 = g_nd_hes[j], e1 = g_nd_hes[j + 1];
            int e2 = g_nd_hes[j + 2], e3 = g_nd_hes[j + 3];
            uint2 u0 = reinterpret_cast<const uint2*>(HEW)[(size_t)e0 * 32 + f4];
            uint2 u1 = reinterpret_cast<const uint2*>(HEW)[(size_t)e1 * 32 + f4];
            uint2 u2 = reinterpret_cast<const uint2*>(HEW)[(size_t)e2 * 32 + f4];
            uint2 u3 = reinterpret_cast<const uint2*>(HEW)[(size_t)e3 * 32 + f4];
            acc_h2(acc, u0); acc_h2(acc, u1); acc_h2(acc, u2); acc_h2(acc, u3);
        }
        for (; j < t; j++)
            acc_h2(acc, reinterpret_cast<const uint2*>(HEW)[(size_t)g_nd_hes[j] * 32 + f4]);
        float inv = (t > s) ? 1.0f / (float)(t - s) : 0.f;
        float4 o;
        o.x = fmaxf(fmaf(acc.x, inv, b4.x), 0.f);
        o.y = fmaxf(fmaf(acc.y, inv, b4.y), 0.f);
        o.z = fmaxf(fmaf(acc.z, inv, b4.z), 0.f);
        o.w = fmaxf(fmaf(acc.w, inv, b4.w), 0.f);
        reinterpret_cast<float4*>(OUT)[(size_t)n * 32 + f4] = o;
    }
}

// ---------------- launch ----------------
extern "C" void kernel_launch(void* const* d_in, const int* in_sizes, int n_in,
                              void* d_out, int out_size) {
    const float* x    = (const float*)d_in[0];
    const int*   edge = (const int*)d_in[1];
    const int*   node_idx = edge;
    const int*   he_idx   = edge + N_INC;
    const float* W1 = (const float*)d_in[2];
    const float* b1 = (const float*)d_in[3];
    const float* g1 = (const float*)d_in[4];
    const float* be1 = (const float*)d_in[5];
    const float* W2 = (const float*)d_in[6];
    const float* b2 = (const float*)d_in[7];
    const float* g2 = (const float*)d_in[8];
    const float* be2 = (const float*)d_in[9];
    const float* W3 = (const float*)d_in[10];
    const float* b3 = (const float*)d_in[11];
    float* out = (float*)d_out;

    void *p_X1, *p_HEW, *p_W1s, *p_W2s, *p_W3s, *p_bnst;
    cudaGetSymbolAddress(&p_X1, g_X1);
    cudaGetSymbolAddress(&p_HEW, g_HEW);
    cudaGetSymbolAddress(&p_W1s, g_W1s);
    cudaGetSymbolAddress(&p_W2s, g_W2s);
    cudaGetSymbolAddress(&p_W3s, g_W3s);
    cudaGetSymbolAddress(&p_bnst, g_bnst);
    __half* X1  = (__half*)p_X1;
    __half* HEW = (__half*)p_HEW;
    __half* W1s = (__half*)p_W1s;
    __half* W2s = (__half*)p_W2s;
    __half* W3s = (__half*)p_W3s;
    float* bnst0 = (float*)p_bnst;
    float* bnst1 = bnst0 + 2 * HID;

    // smem: A chunks (K/64 * 16KB) + 2 * (2 * N*128)
    const int SMEM_L1 = 2 * 16384 + 2 * (2 * 256 * 128);   // 163840
    const int SMEM_L2 = 4 * 16384 + 2 * (2 * 256 * 128);   // 196608
    const int SMEM_L3 = 4 * 16384 + 2 * (2 * 128 * 128);   // 131072
    cudaFuncSetAttribute((const void*)gemm_gather<4, 128, 0>,
                         cudaFuncAttributeMaxDynamicSharedMemorySize, SMEM_L1);
    cudaFuncSetAttribute((const void*)gemm_gather<4, 256, 1>,
                         cudaFuncAttributeMaxDynamicSharedMemorySize, SMEM_L2);
    cudaFuncSetAttribute((const void*)gemm_gather<2, 256, 1>,
                         cudaFuncAttributeMaxDynamicSharedMemorySize, SMEM_L3);
    const int he_tiles = (N_HE + 127) / 128;      // 235
    const int nd_g = (N_NODES + 127) / 128;       // 782

    // ---- weight splits + all zeroing (one launch) ----
    k_split_W_all<<<512, 256>>>(W1, W2, W3);

    // ---- CSR build: hist -> single-kernel scan -> scatter ----
    k_hist<<<(N_INC + 255) / 256, 256>>>(node_idx, he_idx);
    const int nb_nd = (N_NODES + 2047) / 2048;    // 49
    const int nb_he = (N_HE + 2047) / 2048;       // 15
    k_scan_all<<<nb_nd + nb_he, 256>>>(nb_nd);
    k_scatter<<<(N_INC + 255) / 256, 256>>>(node_idx, he_idx);

    // ---- layer 1: gemm(+gather from x) -> node_gather(+bn stats set0) ----
    {
        dim3 grid(1, he_tiles);
        gemm_gather<4, 128, 0><<<grid, 512, SMEM_L1>>>(x, W1s, HEW, N_HE,
                                                       nullptr, nullptr, nullptr);
        k_node_gather_bn<<<nd_g, 256>>>(HEW, b1, X1, bnst0);
    }
    // ---- layer 2: gemm(+gather from X1, BN1 from set0) -> node_gather(+set1) ----
    {
        dim3 grid(1, he_tiles);
        gemm_gather<4, 256, 1><<<grid, 512, SMEM_L2>>>(X1, W2s, HEW, N_HE,
                                                       g1, be1, bnst0);
        k_node_gather_bn<<<nd_g, 256>>>(HEW, b2, X1, bnst1);
    }
    // ---- layer 3: gemm(+gather from X1, BN2 from set1) -> node_gather -> out ----
    {
        dim3 grid(1, he_tiles);
        gemm_gather<2, 256, 1><<<grid, 256, SMEM_L3>>>(X1, W3s, HEW, N_HE,
                                                       g2, be2, bnst1);
        k_node_gather128<<<nd_g, 256>>>(HEW, b3, out);
    }
}